// round 17
// baseline (speedup 1.0000x reference)
#include <cuda_runtime.h>
#include <cuda_fp16.h>
#include <math.h>
#include <stdint.h>

// ---------------- problem constants ----------------
#define BATCH 16
#define IMG 512
#define PATCH 16
#define CIN 3
#define DMODEL 384
#define NHEADS 4
#define HDIM 96
#define NBLOCKS 3
#define NCLS 2
#define NPATCH 1024
#define SEQ 1025
#define FFDIM 1536
#define MROWS (BATCH * SEQ)   // 16400
#define BH (BATCH * NHEADS)   // 64
#define SCALE_ATT 0.10206207261596577f   // 1/sqrt(96)
#define KPATCH (CIN * PATCH * PATCH)     // 768

// ---------------- scratch ----------------
__device__ float  g_h   [(size_t)MROWS * DMODEL];       // fp32 residual stream
__device__ __half g_hn  [(size_t)MROWS * DMODEL];
__device__ __half g_q   [(size_t)MROWS * DMODEL];
__device__ __half g_k   [(size_t)MROWS * DMODEL];
__device__ __half g_v   [(size_t)MROWS * DMODEL];
__device__ __half g_vals[(size_t)MROWS * DMODEL];
__device__ __half g_f   [(size_t)MROWS * FFDIM];
__device__ __half g_xh  [(size_t)BATCH * CIN * IMG * IMG];   // fp16 input image
__device__ __half g_cwc [(size_t)DMODEL * KPATCH];           // fp16 conv_w [N][K]
// fp16 weights, TRANSPOSED to [N][K] (k-contiguous)
__device__ __half g_cwq [(size_t)NBLOCKS * DMODEL * DMODEL];
__device__ __half g_cwk [(size_t)NBLOCKS * DMODEL * DMODEL];
__device__ __half g_cwv [(size_t)NBLOCKS * DMODEL * DMODEL];
__device__ __half g_cwo [(size_t)NBLOCKS * DMODEL * DMODEL];
__device__ __half g_cw1 [(size_t)NBLOCKS * DMODEL * FFDIM];
__device__ __half g_cw2 [(size_t)NBLOCKS * FFDIM * DMODEL];

// ---------------- helpers ----------------
__device__ __forceinline__ float sqrt_approx(float x) {
    float y;
    asm("sqrt.approx.f32 %0, %1;" : "=f"(y) : "f"(x));
    return y;
}
__device__ __forceinline__ uint32_t packh2(float a, float b) {
    __half2 h = __floats2half2_rn(a, b);
    return *(uint32_t*)&h;
}
__device__ __forceinline__ float2 unpackh2(uint32_t u) {
    __half2 h = *(__half2*)&u;
    return __half22float2(h);
}
__device__ __forceinline__ void mma_h(float* d, const uint32_t* a, const uint32_t* b) {
    asm volatile(
        "mma.sync.aligned.m16n8k16.row.col.f32.f16.f16.f32 "
        "{%0,%1,%2,%3}, {%4,%5,%6,%7}, {%8,%9}, {%0,%1,%2,%3};"
        : "+f"(d[0]), "+f"(d[1]), "+f"(d[2]), "+f"(d[3])
        : "r"(a[0]), "r"(a[1]), "r"(a[2]), "r"(a[3]), "r"(b[0]), "r"(b[1]));
}
__device__ __forceinline__ void cpa16(uint32_t dst, const void* src, int srcsize) {
    asm volatile("cp.async.ca.shared.global [%0], [%1], 16, %2;\n"
                 :: "r"(dst), "l"(src), "r"(srcsize));
}
__device__ __forceinline__ void cpa_commit() {
    asm volatile("cp.async.commit_group;\n" ::: "memory");
}
template <int N>
__device__ __forceinline__ void cpa_wait() {
    asm volatile("cp.async.wait_group %0;\n" :: "n"(N) : "memory");
}
__device__ __forceinline__ void ldmx4(uint32_t* r, uint32_t addr) {
    asm volatile("ldmatrix.sync.aligned.m8n8.x4.shared.b16 {%0,%1,%2,%3}, [%4];"
                 : "=r"(r[0]), "=r"(r[1]), "=r"(r[2]), "=r"(r[3]) : "r"(addr));
}
__device__ __forceinline__ void ldmx2(uint32_t* r, uint32_t addr) {
    asm volatile("ldmatrix.sync.aligned.m8n8.x2.shared.b16 {%0,%1}, [%2];"
                 : "=r"(r[0]), "=r"(r[1]) : "r"(addr));
}
__device__ __forceinline__ void ldmx4t(uint32_t* r, uint32_t addr) {
    asm volatile("ldmatrix.sync.aligned.m8n8.x4.trans.shared.b16 {%0,%1,%2,%3}, [%4];"
                 : "=r"(r[0]), "=r"(r[1]), "=r"(r[2]), "=r"(r[3]) : "r"(addr));
}

// epilogue modes
#define E_NONE  0
#define E_RELU  2
#define E_RES   3

// ---------------- fp16 GEMM: BM=128, BK=128, 3-stage, 512 thr, occ 1 ----------------
// A: half [M][K]; B: half [N][K] transposed. C: half or float(E_RES).
// ADDR 0 plain; ADDR 4 fused QKV triple (grid.x = 9).
// smem rows: 128 halves = 64 u32 + 4 pad = stride 68 (68 mod 32 = 4: conflict-free).
template <int EPI, int ADDR, int BN>
__global__ __launch_bounds__(512, 1)
void gemm_h(const __half* __restrict__ Ab, int lda,
            const __half* __restrict__ Bb, int ldb,
            void* __restrict__ Cb, int ldc,
            const float* __restrict__ bias,
            const __half* __restrict__ Bx2, const __half* __restrict__ Bx3,
            void* __restrict__ Cx2, void* __restrict__ Cx3,
            int M, int N, int K)
{
    constexpr int NT  = BN / 32;
    constexpr int RS  = 68;                 // u32 row stride (128 halves + pad)
    constexpr int AST = 128 * RS;
    constexpr int BST = BN * RS;
    constexpr int BCH = BN * 16;            // B 16B chunks per stage

    extern __shared__ uint32_t smh[];
    uint32_t* Asm = smh;
    uint32_t* Bsm = smh + 3 * AST;

    const int tid  = threadIdx.x;
    const int lane = tid & 31;
    const int w    = tid >> 5;
    const int wm   = (w >> 2) * 32;
    const int wn   = (w & 3) * (NT * 8);
    const int m0   = blockIdx.y * 128;
    int n0         = blockIdx.x * BN;

    const __half* A = Ab;
    const __half* B = Bb;
    void* C = Cb;
    if (ADDR == 4) {
        int mat = blockIdx.x / 3;
        n0 = (blockIdx.x % 3) * BN;
        B = (mat == 0) ? Bb : (mat == 1) ? Bx2 : Bx3;
        C = (mat == 0) ? Cb : (mat == 1) ? Cx2 : Cx3;
    }

    const uint32_t as_base = (uint32_t)__cvta_generic_to_shared(Asm);
    const uint32_t bs_base = (uint32_t)__cvta_generic_to_shared(Bsm);

    const int KT = K >> 7;   // BK = 128

    auto issue = [&](int kidx, int stage) {
        // A: 128 rows x 16 chunks = 2048; 4 per thread
#pragma unroll
        for (int j = 0; j < 4; ++j) {
            int id = tid + 512 * j;
            int row = id >> 4, c16 = id & 15;
            int gm2 = m0 + row;
            const __half* ap = A + (size_t)min(gm2, M - 1) * lda + kidx * 128 + c16 * 8;
            cpa16(as_base + (uint32_t)(stage * AST + row * RS + c16 * 4) * 4,
                  ap, (gm2 < M) ? 16 : 0);
        }
        // B: BN*16 chunks (2048 or 1536)
#pragma unroll
        for (int j = 0; j < 4; ++j) {
            int id = tid + 512 * j;
            if (BN == 128 || id < BCH) {
                int row = id >> 4, c16 = id & 15;
                const __half* bp = B + (size_t)(n0 + row) * ldb + kidx * 128 + c16 * 8;
                cpa16(bs_base + (uint32_t)(stage * BST + row * RS + c16 * 4) * 4, bp, 16);
            }
        }
        cpa_commit();
    };

    // ldmatrix lane mappings
    const int alane = (lane & 7) + ((lane >> 3) & 1) * 8;
    const int akoff = (lane >> 4) * 4;
    const int blane = (lane & 7) + (lane >> 4) * 8;
    const int bkoff = ((lane >> 3) & 1) * 4;
    const int b2lane = (lane & 7);
    const int b2koff = ((lane >> 3) & 1) * 4;

    float acc[2][NT][4];
#pragma unroll
    for (int mt = 0; mt < 2; ++mt)
#pragma unroll
        for (int nt = 0; nt < NT; ++nt)
#pragma unroll
            for (int e = 0; e < 4; ++e) acc[mt][nt][e] = 0.f;

    issue(0, 0);
    if (KT > 1) issue(1, 1);

    for (int it = 0; it < KT; ++it) {
        if (it + 1 < KT) cpa_wait<1>(); else cpa_wait<0>();
        __syncthreads();
        if (it + 2 < KT) issue(it + 2, (it + 2) % 3);

        const int st = it % 3;
        const uint32_t a_stage = as_base + (uint32_t)(st * AST) * 4;
        const uint32_t b_stage = bs_base + (uint32_t)(st * BST) * 4;
#pragma unroll
        for (int ks = 0; ks < 8; ++ks) {     // eight k16 steps per BK=128
            uint32_t af[2][4];
#pragma unroll
            for (int mt = 0; mt < 2; ++mt) {
                uint32_t addr = a_stage
                    + (uint32_t)((wm + mt * 16 + alane) * RS + ks * 8 + akoff) * 4;
                ldmx4(af[mt], addr);
            }
            uint32_t bf[NT][2];
#pragma unroll
            for (int p = 0; p < NT / 2; ++p) {
                uint32_t tmp[4];
                uint32_t addr = b_stage
                    + (uint32_t)((wn + p * 16 + blane) * RS + ks * 8 + bkoff) * 4;
                ldmx4(tmp, addr);
                bf[2 * p][0] = tmp[0]; bf[2 * p][1] = tmp[1];
                bf[2 * p + 1][0] = tmp[2]; bf[2 * p + 1][1] = tmp[3];
            }
            if (NT & 1) {
                uint32_t addr = b_stage
                    + (uint32_t)((wn + (NT - 1) * 8 + b2lane) * RS + ks * 8 + b2koff) * 4;
                ldmx2(bf[NT - 1], addr);
            }
#pragma unroll
            for (int nt = 0; nt < NT; ++nt)
#pragma unroll
                for (int mt = 0; mt < 2; ++mt)
                    mma_h(acc[mt][nt], af[mt], bf[nt]);
        }
    }

#pragma unroll
    for (int mt = 0; mt < 2; ++mt) {
#pragma unroll
        for (int nt = 0; nt < NT; ++nt) {
            const int n = n0 + wn + nt * 8 + (lane & 3) * 2;
            const int mlo = m0 + wm + mt * 16 + (lane >> 2);
            const int mhi = mlo + 8;
            float b0 = 0.f, b1 = 0.f;
            if (EPI == E_RELU || EPI == E_RES) { b0 = bias[n]; b1 = bias[n + 1]; }
            if (mlo < M) {
                float v0 = acc[mt][nt][0], v1 = acc[mt][nt][1];
                if (EPI == E_RES) {
                    float2* cp = (float2*)((float*)C + (size_t)mlo * ldc + n);
                    float2 old = *cp;
                    *cp = make_float2(v0 + b0 + old.x, v1 + b1 + old.y);
                } else {
                    if (EPI == E_RELU) { v0 = fmaxf(v0 + b0, 0.f); v1 = fmaxf(v1 + b1, 0.f); }
                    *(uint32_t*)((__half*)C + (size_t)mlo * ldc + n) = packh2(v0, v1);
                }
            }
            if (mhi < M) {
                float v0 = acc[mt][nt][2], v1 = acc[mt][nt][3];
                if (EPI == E_RES) {
                    float2* cp = (float2*)((float*)C + (size_t)mhi * ldc + n);
                    float2 old = *cp;
                    *cp = make_float2(v0 + b0 + old.x, v1 + b1 + old.y);
                } else {
                    if (EPI == E_RELU) { v0 = fmaxf(v0 + b0, 0.f); v1 = fmaxf(v1 + b1, 0.f); }
                    *(uint32_t*)((__half*)C + (size_t)mhi * ldc + n) = packh2(v0, v1);
                }
            }
        }
    }
}

#define GH_SM_128 ((3 * 128 * 68 + 3 * 128 * 68) * 4)   // 208896 B
#define GH_SM_96  ((3 * 128 * 68 + 3 * 96 * 68) * 4)    // 182784 B

// ---------------- fp16 patch embed (round-16, frozen): BK=64 pipeline ----------------
__global__ __launch_bounds__(512, 2)
void patch_h(const __half* __restrict__ Xh, const __half* __restrict__ Wc,
             float* __restrict__ H, const float* __restrict__ cb,
             const float* __restrict__ pos)
{
    constexpr int AST = 128 * 36;
    constexpr int BST = 128 * 36;

    extern __shared__ uint32_t smh[];
    uint32_t* Asm = smh;
    uint32_t* Bsm = smh + 3 * AST;

    const int tid  = threadIdx.x;
    const int lane = tid & 31;
    const int w    = tid >> 5;
    const int wm   = (w >> 2) * 32;
    const int wn   = (w & 3) * 32;
    const int m0   = blockIdx.y * 128;
    const int n0   = blockIdx.x * 128;

    const uint32_t as_base = (uint32_t)__cvta_generic_to_shared(Asm);
    const uint32_t bs_base = (uint32_t)__cvta_generic_to_shared(Bsm);

    const int KT = KPATCH >> 6;   // 12

    auto issue = [&](int kidx, int stage) {
#pragma unroll
        for (int j = 0; j < 2; ++j) {
            int id = tid + 512 * j;
            int row = id >> 3, c16 = id & 7;
            int gm = m0 + row;
            int b = gm >> 10, pix = gm & 1023, hp = pix >> 5, wp = pix & 31;
            int k = kidx * 64 + c16 * 8;
            int c = k >> 8, r = (k >> 4) & 15, q = k & 15;
            const __half* ap = Xh + ((size_t)(b * CIN + c) * IMG + hp * PATCH + r) * IMG
                                  + wp * PATCH + q;
            cpa16(as_base + (uint32_t)(stage * AST + row * 36 + c16 * 4) * 4, ap, 16);
        }
#pragma unroll
        for (int j = 0; j < 2; ++j) {
            int id = tid + 512 * j;
            int row = id >> 3, c16 = id & 7;
            const __half* bp = Wc + (size_t)(n0 + row) * KPATCH + kidx * 64 + c16 * 8;
            cpa16(bs_base + (uint32_t)(stage * BST + row * 36 + c16 * 4) * 4, bp, 16);
        }
        cpa_commit();
    };

    const int alane = (lane & 7) + ((lane >> 3) & 1) * 8;
    const int akoff = (lane >> 4) * 4;
    const int blane = (lane & 7) + (lane >> 4) * 8;
    const int bkoff = ((lane >> 3) & 1) * 4;

    float acc[2][4][4];
#pragma unroll
    for (int mt = 0; mt < 2; ++mt)
#pragma unroll
        for (int nt = 0; nt < 4; ++nt)
#pragma unroll
            for (int e = 0; e < 4; ++e) acc[mt][nt][e] = 0.f;

    issue(0, 0);
    issue(1, 1);

    for (int it = 0; it < KT; ++it) {
        if (it + 1 < KT) cpa_wait<1>(); else cpa_wait<0>();
        __syncthreads();
        if (it + 2 < KT) issue(it + 2, (it + 2) % 3);

        const int st = it % 3;
        const uint32_t a_stage = as_base + (uint32_t)(st * AST) * 4;
        const uint32_t b_stage = bs_base + (uint32_t)(st * BST) * 4;
#pragma unroll
        for (int ks = 0; ks < 4; ++ks) {
            uint32_t af[2][4];
#pragma unroll
            for (int mt = 0; mt < 2; ++mt) {
                uint32_t addr = a_stage
                    + (uint32_t)((wm + mt * 16 + alane) * 36 + ks * 8 + akoff) * 4;
                ldmx4(af[mt], addr);
            }
            uint32_t bf[4][2];
#pragma unroll
            for (int p = 0; p < 2; ++p) {
                uint32_t tmp[4];
                uint32_t addr = b_stage
                    + (uint32_t)((wn + p * 16 + blane) * 36 + ks * 8 + bkoff) * 4;
                ldmx4(tmp, addr);
                bf[2 * p][0] = tmp[0]; bf[2 * p][1] = tmp[1];
                bf[2 * p + 1][0] = tmp[2]; bf[2 * p + 1][1] = tmp[3];
            }
#pragma unroll
            for (int nt = 0; nt < 4; ++nt)
#pragma unroll
                for (int mt = 0; mt < 2; ++mt)
                    mma_h(acc[mt][nt], af[mt], bf[nt]);
        }
    }

#pragma unroll
    for (int mt = 0; mt < 2; ++mt) {
#pragma unroll
        for (int nt = 0; nt < 4; ++nt) {
            const int n = n0 + wn + nt * 8 + (lane & 3) * 2;
#pragma unroll
            for (int half_ = 0; half_ < 2; ++half_) {
                const int m = m0 + wm + mt * 16 + (lane >> 2) + half_ * 8;
                const int b = m >> 10, np = m & 1023;
                const float2 pv = *(const float2*)(pos + (size_t)(1 + np) * DMODEL + n);
                float v0 = acc[mt][nt][half_ * 2]     + cb[n]     + pv.x;
                float v1 = acc[mt][nt][half_ * 2 + 1] + cb[n + 1] + pv.y;
                *(float2*)(H + ((size_t)b * SEQ + 1 + np) * DMODEL + n) =
                    make_float2(v0, v1);
            }
        }
    }
}
#define PATCH_SM ((3 * 128 * 36 + 3 * 128 * 36) * 4)

// ---------------- flash attention fp16 (round-15, frozen) ----------------
#define KTILES 17
#define KVL 104
#define KV_ST (64 * KVL)
#define FLASH_SMEM ((4 * KV_ST) * 2 + 2 * 64 * 4)

__global__ __launch_bounds__(256, 2)
void flash_kernel(const __half* __restrict__ Qg, const __half* __restrict__ Kg,
                  const __half* __restrict__ Vg, __half* __restrict__ Og)
{
    extern __shared__ __half smf[];
    __half* Ks = smf;
    __half* Vs = smf + 2 * KV_ST;
    float*  kks = (float*)(smf + 4 * KV_ST);

    const int z = blockIdx.y, b = z >> 2, hh = z & 3;
    const int q0 = blockIdx.x * 128;
    const int tid = threadIdx.x, lane = tid & 31, w = tid >> 5;
    const int rr = q0 + w * 16 + (lane >> 2);

    const uint32_t ks_base = (uint32_t)__cvta_generic_to_shared(Ks);
    const uint32_t vs_base = (uint32_t)__cvta_generic_to_shared(Vs);

    auto issue_kv = [&](int kt, int st) {
#pragma unroll
        for (int j = 0; j < 3; ++j) {
            int i = tid + j * 256;
            int t = i / 12, c = i % 12;
            int tg = kt * 64 + t;
            int sz = (tg < SEQ) ? 16 : 0;
            int tgc = min(tg, SEQ - 1);
            const __half* kp = Kg + ((size_t)b * SEQ + tgc) * DMODEL + hh * HDIM + c * 8;
            const __half* vp = Vg + ((size_t)b * SEQ + tgc) * DMODEL + hh * HDIM + c * 8;
            uint32_t off = (uint32_t)(t * KVL + c * 8) * 2;
            cpa16(ks_base + (uint32_t)st * (KV_ST * 2) + off, kp, sz);
            cpa16(vs_base + (uint32_t)st * (KV_ST * 2) + off, vp, sz);
        }
        cpa_commit();
    };

    auto compute_kk = [&](int st) {
        int t = tid >> 2, part = tid & 3;
        const uint32_t* kr = (const uint32_t*)(Ks + st * KV_ST + t * KVL) + part * 12;
        float sk = 0.f;
#pragma unroll
        for (int d = 0; d < 12; ++d) {
            float2 f = unpackh2(kr[d]);
            sk = fmaf(f.x, f.x, sk);
            sk = fmaf(f.y, f.y, sk);
        }
        sk += __shfl_xor_sync(0xffffffffu, sk, 1);
        sk += __shfl_xor_sync(0xffffffffu, sk, 2);
        if (part == 0) kks[st * 64 + t] = sk;
    };

    const int r0c = min(rr, SEQ - 1), r1c = min(rr + 8, SEQ - 1);
    const uint32_t* q0p = (const uint32_t*)(Qg + ((size_t)b * SEQ + r0c) * DMODEL + hh * HDIM);
    const uint32_t* q1p = (const uint32_t*)(Qg + ((size_t)b * SEQ + r1c) * DMODEL + hh * HDIM);
    uint32_t qf[6][4];
#pragma unroll
    for (int s = 0; s < 6; ++s) {
        int c0 = s * 8 + (lane & 3);
        qf[s][0] = q0p[c0];
        qf[s][1] = q1p[c0];
        qf[s][2] = q0p[c0 + 4];
        qf[s][3] = q1p[c0 + 4];
    }
    float qq0 = 0.f, qq1 = 0.f;
#pragma unroll
    for (int s = 0; s < 6; ++s) {
        float2 f0 = unpackh2(qf[s][0]), f2 = unpackh2(qf[s][2]);
        float2 f1 = unpackh2(qf[s][1]), f3 = unpackh2(qf[s][3]);
        qq0 = fmaf(f0.x, f0.x, qq0); qq0 = fmaf(f0.y, f0.y, qq0);
        qq0 = fmaf(f2.x, f2.x, qq0); qq0 = fmaf(f2.y, f2.y, qq0);
        qq1 = fmaf(f1.x, f1.x, qq1); qq1 = fmaf(f1.y, f1.y, qq1);
        qq1 = fmaf(f3.x, f3.x, qq1); qq1 = fmaf(f3.y, f3.y, qq1);
    }
    qq0 += __shfl_xor_sync(0xffffffffu, qq0, 1);
    qq0 += __shfl_xor_sync(0xffffffffu, qq0, 2);
    qq1 += __shfl_xor_sync(0xffffffffu, qq1, 1);
    qq1 += __shfl_xor_sync(0xffffffffu, qq1, 2);

    float o[12][4];
#pragma unroll
    for (int n = 0; n < 12; ++n)
#pragma unroll
        for (int e = 0; e < 4; ++e) o[n][e] = 0.f;
    float l0 = 0.f, l1 = 0.f;

    issue_kv(0, 0);
    cpa_wait<0>();
    __syncthreads();
    compute_kk(0);
    __syncthreads();

    const int blane = (lane & 7) + (lane >> 4) * 8;
    const int bkoff = ((lane >> 3) & 1) * 4;

    for (int kt = 0; kt < KTILES; ++kt) {
        const int st = kt & 1;
        const bool more = (kt + 1 < KTILES);

        if (more) issue_kv(kt + 1, st ^ 1);

        float sc[8][4];
#pragma unroll
        for (int nt = 0; nt < 8; ++nt)
#pragma unroll
            for (int e = 0; e < 4; ++e) sc[nt][e] = 0.f;

        const uint32_t k_stage = ks_base + (uint32_t)st * (KV_ST * 2);
#pragma unroll
        for (int s = 0; s < 6; ++s) {
            uint32_t bf[8][2];
#pragma unroll
            for (int p = 0; p < 4; ++p) {
                uint32_t tmp[4];
                uint32_t addr = k_stage
                    + (uint32_t)((p * 16 + blane) * 52 + s * 8 + bkoff) * 4;
                ldmx4(tmp, addr);
                bf[2 * p][0] = tmp[0]; bf[2 * p][1] = tmp[1];
                bf[2 * p + 1][0] = tmp[2]; bf[2 * p + 1][1] = tmp[3];
            }
#pragma unroll
            for (int nt = 0; nt < 8; ++nt)
                mma_h(sc[nt], qf[s], bf[nt]);
        }

        const float* kkst = kks + st * 64;
        float s0 = 0.f, s1 = 0.f;
#pragma unroll
        for (int nt = 0; nt < 8; ++nt) {
#pragma unroll
            for (int e = 0; e < 4; ++e) {
                int colL = nt * 8 + 2 * (lane & 3) + (e & 1);
                int colG = kt * 64 + colL;
                float qv = (e < 2) ? qq0 : qq1;
                float d2 = qv + kkst[colL] - 2.f * sc[nt][e];
                float sv = sqrt_approx(fmaxf(d2, 1e-30f)) * SCALE_ATT;
                float p = (colG < SEQ) ? __expf(sv) : 0.f;
                if (e < 2) s0 += p; else s1 += p;
                sc[nt][e] = p;
            }
        }
        s0 += __shfl_xor_sync(0xffffffffu, s0, 1);
        s0 += __shfl_xor_sync(0xffffffffu, s0, 2);
        s1 += __shfl_xor_sync(0xffffffffu, s1, 1);
        s1 += __shfl_xor_sync(0xffffffffu, s1, 2);
        l0 += s0;
        l1 += s1;

        const int grp = lane >> 3, rowin = lane & 7;
#pragma unroll
        for (int kappa = 0; kappa < 4; ++kappa) {
            uint32_t af[4];
            af[0] = packh2(sc[2 * kappa][0],     sc[2 * kappa][1]);
            af[1] = packh2(sc[2 * kappa][2],     sc[2 * kappa][3]);
            af[2] = packh2(sc[2 * kappa + 1][0], sc[2 * kappa + 1][1]);
            af[3] = packh2(sc[2 * kappa + 1][2], sc[2 * kappa + 1][3]);
            int tbase2 = kappa * 16 + (grp & 1) * 8 + rowin;
#pragma unroll
            for (int nt2 = 0; nt2 < 6; ++nt2) {
                int d8 = nt2 * 16 + (grp >> 1) * 8;
                uint32_t vb[4];
                uint32_t addr = vs_base + (uint32_t)(st * KV_ST + tbase2 * KVL + d8) * 2;
                ldmx4t(vb, addr);
                mma_h(o[nt2 * 2],     af, vb);
                mma_h(o[nt2 * 2 + 1], af, vb + 2);
            }
        }

        if (more) {
            cpa_wait<0>();
            __syncthreads();
            compute_kk(st ^ 1);
        }
        __syncthreads();
    }

    float inv0 = 1.f / l0, inv1 = 1.f / l1;
    if (rr < SEQ) {
        __half* orow = Og + ((size_t)b * SEQ + rr) * DMODEL + hh * HDIM;
#pragma unroll
        for (int nt = 0; nt < 12; ++nt) {
            int col = nt * 8 + 2 * (lane & 3);
            *(uint32_t*)(orow + col) = packh2(o[nt][0] * inv0, o[nt][1] * inv0);
        }
    }
    if (rr + 8 < SEQ) {
        __half* orow = Og + ((size_t)b * SEQ + rr + 8) * DMODEL + hh * HDIM;
#pragma unroll
        for (int nt = 0; nt < 12; ++nt) {
            int col = nt * 8 + 2 * (lane & 3);
            *(uint32_t*)(orow + col) = packh2(o[nt][2] * inv1, o[nt][3] * inv1);
        }
    }
}

// ---------------- prep (round-16, frozen) ----------------
#define T_SMALL (4 * NBLOCKS * 144)
#define T_W1    (NBLOCKS * 576)
#define T_W2    (NBLOCKS * 576)
#define T_WALL  (T_SMALL + T_W1 + T_W2)
#define T_CONVC (DMODEL * KPATCH / 1024)
#define T_XCONV (BATCH * CIN * IMG * IMG / 1024)
#define T_CLS   ((BATCH * DMODEL + 255) / 256)
__global__ void prep_kernel(
    const float* __restrict__ wq, const float* __restrict__ wk,
    const float* __restrict__ wv, const float* __restrict__ wo,
    const float* __restrict__ w1, const float* __restrict__ w2,
    __half* __restrict__ dq, __half* __restrict__ dk, __half* __restrict__ dv,
    __half* __restrict__ dw, __half* __restrict__ d1, __half* __restrict__ d2,
    const float* __restrict__ cw, __half* __restrict__ cwh,
    const float* __restrict__ x, __half* __restrict__ xh,
    const float* __restrict__ cls_tok, const float* __restrict__ pos,
    float* __restrict__ h)
{
    int id = blockIdx.x;

    if (id < T_WALL) {
        __shared__ float t[32][33];
        int tx = threadIdx.x & 31, ty = threadIdx.x >> 5;
        const float* in; __half* out; int Kd, Nd, tk, tn, layer;
        if (id < T_SMALL) {
            int mat = id / (NBLOCKS * 144);
            int r = id % (NBLOCKS * 144);
            layer = r / 144;
            int tile = r % 144;
            tk = tile % 12; tn = tile / 12;
            Kd = DMODEL; Nd = DMODEL;
            const float* srcs0 = (mat == 0) ? wq : (mat == 1) ? wk : (mat == 2) ? wv : wo;
            __half* dsts0 = (mat == 0) ? dq : (mat == 1) ? dk : (mat == 2) ? dv : dw;
            in = srcs0 + (size_t)layer * DMODEL * DMODEL;
            out = dsts0 + (size_t)layer * DMODEL * DMODEL;
        } else if (id < T_SMALL + T_W1) {
            int r = id - T_SMALL;
            layer = r / 576;
            int tile = r % 576;
            tk = tile % 12; tn = tile / 12;
            Kd = DMODEL; Nd = FFDIM;
            in = w1 + (size_t)layer * DMODEL * FFDIM;
            out = d1 + (size_t)layer * DMODEL * FFDIM;
        } else {
            int r = id - T_SMALL - T_W1;
            layer = r / 576;
            int tile = r % 576;
            tk = tile % 48; tn = tile / 48;
            Kd = FFDIM; Nd = DMODEL;
            in = w2 + (size_t)layer * FFDIM * DMODEL;
            out = d2 + (size_t)layer * FFDIM * DMODEL;
        }
        int k0 = tk * 32, n0 = tn * 32;
        for (int i = ty; i < 32; i += 8)
            t[i][tx] = in[(size_t)(k0 + i) * Nd + n0 + tx];
        __syncthreads();
        for (int i = ty; i < 32; i += 8)
            out[(size_t)(n0 + i) * Kd + k0 + tx] = __float2half_rn(t[tx][i]);
    } else if (id < T_WALL + T_CONVC) {
        int i = (id - T_WALL) * 256 + threadIdx.x;
        float4 v = ((const float4*)cw)[i];
        __half2 lo = __floats2half2_rn(v.x, v.y);
        __half2 hi = __floats2half2_rn(v.z, v.w);
        ((__half2*)cwh)[i * 2]     = lo;
        ((__half2*)cwh)[i * 2 + 1] = hi;
    } else if (id < T_WALL + T_CONVC + T_XCONV) {
        int i = (id - T_WALL - T_CONVC) * 256 + threadIdx.x;
        float4 v = ((const float4*)x)[i];
        __half2 lo = __floats2half2_rn(v.x, v.y);
        __half2 hi = __floats2half2_rn(v.z, v.w);
        ((__half2*)xh)[i * 2]     = lo;
        ((__half2*)xh)[i * 2 + 1] = hi;
    } else {
        int i = (id - T_WALL - T_CONVC - T_XCONV) * 256 + threadIdx.x;
        if (i < BATCH * DMODEL) {
            int b = i / DMODEL, d = i % DMODEL;
            h[(size_t)b * SEQ * DMODEL + d] = cls_tok[d] + pos[d];
        }
    }
}

// ---------------- LayerNorm: fp32 in -> fp16 out, warp per row ----------------
__global__ void ln_kernel(const float* __restrict__ x, __half* __restrict__ y,
                          const float* __restrict__ s, const float* __restrict__ bb)
{
    int w = threadIdx.x >> 5, lane = threadIdx.x & 31;
    int row = blockIdx.x * 8 + w;
    const float4* xr = (const float4*)(x + (size_t)row * DMODEL);
    uint2* yr = (uint2*)(y + (size_t)row * DMODEL);

    float4 a = xr[lane], c = xr[lane + 32], d = xr[lane + 64];
    float sum = a.x + a.y + a.z + a.w + c.x + c.y + c.z + c.w + d.x + d.y + d.z + d.w;
#pragma unroll
    for (int o = 16; o > 0; o >>= 1) sum += __shfl_xor_sync(0xffffffffu, sum, o);
    float mean = sum * (1.f / DMODEL);

    a.x -= mean; a.y -= mean; a.z -= mean; a.w -= mean;
    c.x -= mean; c.y -= mean; c.z -= mean; c.w -= mean;
    d.x -= mean; d.y -= mean; d.z -= mean; d.w -= mean;
    float sq = a.x*a.x + a.y*a.y + a.z*a.z + a.w*a.w
             + c.x*c.x + c.y*c.y + c.z*c.z + c.w*c.w
             + d.x*d.x + d.y*d.y + d.z*d.z + d.w*d.w;
#pragma unroll
    for (int o = 16; o > 0; o >>= 1) sq += __shfl_xor_sync(0xffffffffu, sq, o);
    float inv = rsqrtf(sq * (1.f / DMODEL) + 1e-5f);

    const float4* sp = (const float4*)s;
    const float4* bp = (const float4*)bb;
    float4 s0 = sp[lane], s1 = sp[lane + 32], s2 = sp[lane + 64];
    float4 b0 = bp[lane], b1 = bp[lane + 32], b2 = bp[lane + 64];
    uint2 r;
    r.x = packh2(a.x*inv*s0.x + b0.x, a.y*inv*s0.y + b0.y);
    r.y = packh2(a.z*inv*s0.z + b0.z, a.w*inv*s0.w + b0.w);
    yr[lane] = r;
    r.x = packh2(c.x*inv*s1.x + b1.x, c.y*inv*s1.y + b1.y);
    r.y = packh2(c.z*inv*s1.z + b1.z, c.w*inv*s1.w + b1.w);
    yr[lane + 32] = r;
    r.x = packh2(d.x*inv*s2.x + b2.x, d.y*inv*s2.y + b2.y);
    r.y = packh2(d.z*inv*s2.z + b2.z, d.w*inv*s2.w + b2.w);
    yr[lane + 64] = r;
}

// ---------------- final LN(cls) + proj + loss ----------------
__global__ void final_kernel(const float* __restrict__ h,
                             const float* __restrict__ lnf_s, const float* __restrict__ lnf_b,
                             const float* __restrict__ pw, const float* __restrict__ pb,
                             const int* __restrict__ targets,
                             float* __restrict__ out, int out_size)
{
    int tid = threadIdx.x;
    __shared__ float losses[BATCH];
    if (tid < BATCH) {
        const float* xr = h + (size_t)tid * SEQ * DMODEL;
        float sum = 0.f;
        for (int d = 0; d < DMODEL; ++d) sum += xr[d];
        float mean = sum * (1.f / DMODEL);
        float sq = 0.f;
        for (int d = 0; d < DMODEL; ++d) {
            float dv = xr[d] - mean;
            sq += dv * dv;
        }
        float inv = rsqrtf(sq * (1.f / DMODEL) + 1e-5f);
        float l0 = pb[0], l1 = pb[1];
        for (int d = 0; d < DMODEL; ++d) {
            float nd = (xr[d] - mean) * inv * lnf_s[d] + lnf_b[d];
            l0 += nd * pw[d * NCLS + 0];
            l1 += nd * pw[d * NCLS + 1];
        }
        out[tid * 2 + 0] = l0;
        out[tid * 2 + 1] = l1;
        float mxl = fmaxf(l0, l1);
        float lse = mxl + logf(expf(l0 - mxl) + expf(l1 - mxl));
        int t = targets[tid];
        losses[tid] = lse - (t == 0 ? l0 : l1);
    }
    __syncthreads();
    if (tid == 0) {
        float s = 0.f;
        for (int i = 0; i < BATCH; ++i) s += losses[i];
        if (out_size > BATCH * NCLS) out[BATCH * NCLS] = s * (1.f / BATCH);
    }
}

// ---------------- launch ----------------
extern "C" void kernel_launch(void* const* d_in, const int* in_sizes, int n_in,
                              void* d_out, int out_size)
{
    const float* x       = (const float*)d_in[0];
    const int*   targets = (const int*)  d_in[1];
    const float* conv_w  = (const float*)d_in[2];
    const float* conv_b  = (const float*)d_in[3];
    const float* cls_tok = (const float*)d_in[4];
    const float* pos_emb = (const float*)d_in[5];
    const float* ln1_s   = (const float*)d_in[6];
    const float* ln1_b   = (const float*)d_in[7];
    const float* ln2_s   = (const float*)d_in[8];
    const float* ln2_b   = (const float*)d_in[9];
    const float* wq      = (const float*)d_in[10];
    const float* wk      = (const float*)d_in[11];
    const float* wv      = (const float*)d_in[12];
    const float* wo      = (const float*)d_in[13];
    const float* bo      = (const float*)d_in[14];
    const float* w1      = (const float*)d_in[15];
    const float* b1      = (const float*)d_in[16];
    const float* w2      = (const float*)d_in[17];
    const float* b2      = (const float*)d_in[18];
    const float* lnf_s   = (const float*)d_in[19];
    const float* lnf_b   = (const float*)d_in[20];
    const float* proj_w  = (const float*)d_in[21];
    const float* proj_b  = (const float*)d_in[22];

    float *h;
    __half *hn, *q, *k, *v, *vals, *f, *xh, *cwh;
    __half *cwq, *cwk, *cwv, *cwo, *cw1, *cw2;
    cudaGetSymbolAddress((void**)&h,    g_h);
    cudaGetSymbolAddress((void**)&hn,   g_hn);
    cudaGetSymbolAddress((void**)&q,    g_q);
    cudaGetSymbolAddress((void**)&k,    g_k);
    cudaGetSymbolAddress((void**)&v,    g_v);
    cudaGetSymbolAddress((void**)&vals, g_vals);
    cudaGetSymbolAddress((void**)&f,    g_f);
    cudaGetSymbolAddress((void**)&xh,   g_xh);
    cudaGetSymbolAddress((void**)&cwh,  g_cwc);
    cudaGetSymbolAddress((void**)&cwq,  g_cwq);
    cudaGetSymbolAddress((void**)&cwk,  g_cwk);
    cudaGetSymbolAddress((void**)&cwv,  g_cwv);
    cudaGetSymbolAddress((void**)&cwo,  g_cwo);
    cudaGetSymbolAddress((void**)&cw1,  g_cw1);
    cudaGetSymbolAddress((void**)&cw2,  g_cw2);

    cudaFuncSetAttribute(flash_kernel,
                         cudaFuncAttributeMaxDynamicSharedMemorySize, FLASH_SMEM);
    cudaFuncSetAttribute(gemm_h<E_NONE, 4, 128>,
                         cudaFuncAttributeMaxDynamicSharedMemorySize, GH_SM_128);
    cudaFuncSetAttribute(gemm_h<E_RELU, 0, 128>,
                         cudaFuncAttributeMaxDynamicSharedMemorySize, GH_SM_128);
    cudaFuncSetAttribute(gemm_h<E_RES, 0, 96>,
                         cudaFuncAttributeMaxDynamicSharedMemorySize, GH_SM_96);
    cudaFuncSetAttribute(patch_h,
                         cudaFuncAttributeMaxDynamicSharedMemorySize, PATCH_SM);

    prep_kernel<<<T_WALL + T_CONVC + T_XCONV + T_CLS, 256>>>(
        wq, wk, wv, wo, w1, w2, cwq, cwk, cwv, cwo, cw1, cw2,
        conv_w, cwh, x, xh, cls_tok, pos_emb, h);

    patch_h<<<dim3(3, 128), 512, PATCH_SM>>>(xh, cwh, h, conv_b, pos_emb);

    const int MT = (MROWS + 127) / 128;  // 129
    for (int i = 0; i < NBLOCKS; ++i) {
        const __half* wqi = cwq + (size_t)i * DMODEL * DMODEL;
        const __half* wki = cwk + (size_t)i * DMODEL * DMODEL;
        const __half* wvi = cwv + (size_t)i * DMODEL * DMODEL;
        const __half* woi = cwo + (size_t)i * DMODEL * DMODEL;
        const __half* w1i = cw1 + (size_t)i * DMODEL * FFDIM;
        const __half* w2i = cw2 + (size_t)i * FFDIM * DMODEL;

        ln_kernel<<<MROWS / 8, 256>>>(h, hn, ln1_s + i * DMODEL, ln1_b + i * DMODEL);

        gemm_h<E_NONE, 4, 128><<<dim3(9, MT), 512, GH_SM_128>>>(
            hn, DMODEL, wqi, DMODEL, q, DMODEL, nullptr,
            wki, wvi, k, v, MROWS, DMODEL, DMODEL);

        flash_kernel<<<dim3(9, BH), 256, FLASH_SMEM>>>(q, k, v, vals);

        gemm_h<E_RES, 0, 96><<<dim3(4, MT), 512, GH_SM_96>>>(
            vals, DMODEL, woi, DMODEL, h, DMODEL, bo + i * DMODEL,
            nullptr, nullptr, nullptr, nullptr, MROWS, DMODEL, DMODEL);

        ln_kernel<<<MROWS / 8, 256>>>(h, hn, ln2_s + i * DMODEL, ln2_b + i * DMODEL);

        gemm_h<E_RELU, 0, 128><<<dim3(12, MT), 512, GH_SM_128>>>(
            hn, DMODEL, w1i, DMODEL, f, FFDIM, b1 + i * FFDIM,
            nullptr, nullptr, nullptr, nullptr, MROWS, FFDIM, DMODEL);

        gemm_h<E_RES, 0, 96><<<dim3(4, MT), 512, GH_SM_96>>>(
            f, FFDIM, w2i, FFDIM, h, DMODEL, b2 + i * DMODEL,
            nullptr, nullptr, nullptr, nullptr, MROWS, DMODEL, FFDIM);
    }

    final_kernel<<<1, 32>>>(h, lnf_s, lnf_b, proj_w, proj_b, targets,
                            (float*)d_out, out_size);
}